// round 4
// baseline (speedup 1.0000x reference)
#include <cuda_runtime.h>

// Problem constants (from reference): image [1,128,128,512] f32 NHWC,
// RoI [N,4] f32 (cx, cy, w, h), N=1000, POOL=7, STRIDE=16.
#define POOL   7
#define HH     128
#define WW     128
#define CC     512
#define NMAX   1024

// Scratch (allocation-free rule: __device__ globals).
__device__ int   g_iy0[NMAX * POOL];
__device__ int   g_iy1[NMAX * POOL];
__device__ float g_ly [NMAX * POOL];
__device__ int   g_ix0[NMAX * POOL];
__device__ int   g_ix1[NMAX * POOL];
__device__ float g_lx [NMAX * POOL];

// ---------------------------------------------------------------------------
// Kernel 1: per-ROI bilinear sample coordinates (matches reference exactly).
//   r  = round((cx - w/2)/16)        (jnp.round == round-half-even == rintf)
//   c  = round((cy - h/2)/16)
//   wq = max(round(w/16), 1), hq likewise
//   s  = ((p+0.5)/7)*size - 0.5, clipped to [0, size-1]
//   f0 = floor(s); frac = s - f0; f1 = min(f0+1, size-1)
//   i0 = clip(start + f0, 0, limit-1) -> int32 ; i1 likewise
// ---------------------------------------------------------------------------
__global__ void roi_coords_kernel(const float* __restrict__ roi, int N)
{
    int n = blockIdx.x * blockDim.x + threadIdx.x;
    if (n >= N) return;

    const float inv_stride = 1.0f / 16.0f;
    float cx = roi[n * 4 + 0];
    float cy = roi[n * 4 + 1];
    float w  = roi[n * 4 + 2];
    float h  = roi[n * 4 + 3];

    float r  = rintf((cx - 0.5f * w) * inv_stride);   // x-start (col)
    float c  = rintf((cy - 0.5f * h) * inv_stride);   // y-start (row)
    float wq = fmaxf(rintf(w * inv_stride), 1.0f);
    float hq = fmaxf(rintf(h * inv_stride), 1.0f);

    #pragma unroll
    for (int p = 0; p < POOL; ++p) {
        float g = (p + 0.5f) / (float)POOL;

        // y axis (rows, limit = HH)
        {
            float s  = g * hq - 0.5f;
            s = fminf(fmaxf(s, 0.0f), hq - 1.0f);
            float f0 = floorf(s);
            float fr = s - f0;
            float f1 = fminf(f0 + 1.0f, hq - 1.0f);
            float i0 = fminf(fmaxf(c + f0, 0.0f), (float)(HH - 1));
            float i1 = fminf(fmaxf(c + f1, 0.0f), (float)(HH - 1));
            g_iy0[n * POOL + p] = (int)i0;
            g_iy1[n * POOL + p] = (int)i1;
            g_ly [n * POOL + p] = fr;
        }
        // x axis (cols, limit = WW)
        {
            float s  = g * wq - 0.5f;
            s = fminf(fmaxf(s, 0.0f), wq - 1.0f);
            float f0 = floorf(s);
            float fr = s - f0;
            float f1 = fminf(f0 + 1.0f, wq - 1.0f);
            float i0 = fminf(fmaxf(r + f0, 0.0f), (float)(WW - 1));
            float i1 = fminf(fmaxf(r + f1, 0.0f), (float)(WW - 1));
            g_ix0[n * POOL + p] = (int)i0;
            g_ix1[n * POOL + p] = (int)i1;
            g_lx [n * POOL + p] = fr;
        }
    }
}

// ---------------------------------------------------------------------------
// Kernel 2: bilinear gather + blend over the 512-channel vectors.
// One CTA per (roi, py, px); 128 threads x float4 = 512 channels.
// Streaming store (__stcs) keeps the 100MB output from evicting the 32MB
// input from L2.
// ---------------------------------------------------------------------------
__global__ __launch_bounds__(128)
void roi_pool_kernel(const float* __restrict__ img, float* __restrict__ out)
{
    int b   = blockIdx.x;
    int n   = b / (POOL * POOL);
    int rem = b - n * (POOL * POOL);
    int py  = rem / POOL;
    int px  = rem - py * POOL;

    int   iy0 = g_iy0[n * POOL + py];
    int   iy1 = g_iy1[n * POOL + py];
    float ly  = g_ly [n * POOL + py];
    int   ix0 = g_ix0[n * POOL + px];
    int   ix1 = g_ix1[n * POOL + px];
    float lx  = g_lx [n * POOL + px];

    float w00 = (1.0f - ly) * (1.0f - lx);
    float w01 = (1.0f - ly) * lx;
    float w10 = ly * (1.0f - lx);
    float w11 = ly * lx;

    const float4* p00 = (const float4*)(img + ((size_t)iy0 * WW + ix0) * CC);
    const float4* p01 = (const float4*)(img + ((size_t)iy0 * WW + ix1) * CC);
    const float4* p10 = (const float4*)(img + ((size_t)iy1 * WW + ix0) * CC);
    const float4* p11 = (const float4*)(img + ((size_t)iy1 * WW + ix1) * CC);
    float4*       po  = (float4*)(out + (size_t)b * CC);

    int t = threadIdx.x;

    float4 a = __ldg(p00 + t);
    float4 bb = __ldg(p01 + t);
    float4 c = __ldg(p10 + t);
    float4 d = __ldg(p11 + t);

    float4 rv;
    rv.x = w00 * a.x + w01 * bb.x + w10 * c.x + w11 * d.x;
    rv.y = w00 * a.y + w01 * bb.y + w10 * c.y + w11 * d.y;
    rv.z = w00 * a.z + w01 * bb.z + w10 * c.z + w11 * d.z;
    rv.w = w00 * a.w + w01 * bb.w + w10 * c.w + w11 * d.w;

    __stcs(po + t, rv);
}

extern "C" void kernel_launch(void* const* d_in, const int* in_sizes, int n_in,
                              void* d_out, int out_size)
{
    const float* img = (const float*)d_in[0];   // [1,128,128,512] f32
    const float* roi = (const float*)d_in[1];   // [N,4] f32
    float*       out = (float*)d_out;           // [1,N,7,7,512] f32

    int N = in_sizes[1] / 4;
    if (N > NMAX) N = NMAX;

    roi_coords_kernel<<<(N + 255) / 256, 256>>>(roi, N);
    roi_pool_kernel<<<N * POOL * POOL, 128>>>(img, out);
}

// round 5
// speedup vs baseline: 1.1089x; 1.1089x over previous
#include <cuda_runtime.h>

// image [1,128,128,512] f32 NHWC, RoI [N,4] f32 (cx,cy,w,h), POOL=7, STRIDE=16.
#define POOL   7
#define HH     128
#define WW     128
#define CC     512
#define NMAX   1024
#define CPC    8          // cells per CTA (49000 % 8 handled by guarded path)
#define THREADS 256

// Scratch (__device__ globals per allocation-free rule).
__device__ int   g_iy0[NMAX * POOL];
__device__ int   g_iy1[NMAX * POOL];
__device__ float g_ly [NMAX * POOL];
__device__ int   g_ix0[NMAX * POOL];
__device__ int   g_ix1[NMAX * POOL];
__device__ float g_lx [NMAX * POOL];

// ---------------------------------------------------------------------------
// Kernel 1: per-ROI bilinear sample coordinates (matches reference exactly).
// ---------------------------------------------------------------------------
__global__ void roi_coords_kernel(const float* __restrict__ roi, int N)
{
    int n = blockIdx.x * blockDim.x + threadIdx.x;
    if (n >= N) return;

    const float inv_stride = 1.0f / 16.0f;
    float cx = roi[n * 4 + 0];
    float cy = roi[n * 4 + 1];
    float w  = roi[n * 4 + 2];
    float h  = roi[n * 4 + 3];

    float r  = rintf((cx - 0.5f * w) * inv_stride);   // x-start (col)
    float c  = rintf((cy - 0.5f * h) * inv_stride);   // y-start (row)
    float wq = fmaxf(rintf(w * inv_stride), 1.0f);
    float hq = fmaxf(rintf(h * inv_stride), 1.0f);

    #pragma unroll
    for (int p = 0; p < POOL; ++p) {
        float g = (p + 0.5f) / (float)POOL;
        {   // y axis (rows, limit HH)
            float s  = fminf(fmaxf(g * hq - 0.5f, 0.0f), hq - 1.0f);
            float f0 = floorf(s);
            float fr = s - f0;
            float f1 = fminf(f0 + 1.0f, hq - 1.0f);
            g_iy0[n * POOL + p] = (int)fminf(fmaxf(c + f0, 0.0f), (float)(HH - 1));
            g_iy1[n * POOL + p] = (int)fminf(fmaxf(c + f1, 0.0f), (float)(HH - 1));
            g_ly [n * POOL + p] = fr;
        }
        {   // x axis (cols, limit WW)
            float s  = fminf(fmaxf(g * wq - 0.5f, 0.0f), wq - 1.0f);
            float f0 = floorf(s);
            float fr = s - f0;
            float f1 = fminf(f0 + 1.0f, wq - 1.0f);
            g_ix0[n * POOL + p] = (int)fminf(fmaxf(r + f0, 0.0f), (float)(WW - 1));
            g_ix1[n * POOL + p] = (int)fminf(fmaxf(r + f1, 0.0f), (float)(WW - 1));
            g_lx [n * POOL + p] = fr;
        }
    }
}

// ---------------------------------------------------------------------------
// Kernel 2: 8 cells per CTA, 256 threads, 4 float4 items/thread fully
// unrolled -> 16 independent LDG.128 in flight per thread (latency hiding).
// Cell params precomputed into smem by 8 threads (kills per-thread IMADs).
// ---------------------------------------------------------------------------
__global__ __launch_bounds__(THREADS)
void roi_pool_kernel(const float* __restrict__ img, float* __restrict__ out,
                     int totalCells)
{
    __shared__ int4   s_off[CPC];   // corner offsets in float4 units
    __shared__ float4 s_w[CPC];     // bilinear weights

    const int base = blockIdx.x * CPC;
    const int tid  = threadIdx.x;

    if (tid < CPC) {
        int cell = base + tid;
        if (cell < totalCells) {
            int n   = cell / (POOL * POOL);
            int rem = cell - n * (POOL * POOL);
            int py  = rem / POOL;
            int px  = rem - py * POOL;

            int   iy0 = g_iy0[n * POOL + py];
            int   iy1 = g_iy1[n * POOL + py];
            float ly  = g_ly [n * POOL + py];
            int   ix0 = g_ix0[n * POOL + px];
            int   ix1 = g_ix1[n * POOL + px];
            float lx  = g_lx [n * POOL + px];

            // float4-unit offsets: (iy*WW + ix) * (CC/4)
            s_off[tid] = make_int4((iy0 * WW + ix0) * (CC / 4),
                                   (iy0 * WW + ix1) * (CC / 4),
                                   (iy1 * WW + ix0) * (CC / 4),
                                   (iy1 * WW + ix1) * (CC / 4));
            s_w[tid] = make_float4((1.0f - ly) * (1.0f - lx),
                                   (1.0f - ly) * lx,
                                   ly * (1.0f - lx),
                                   ly * lx);
        }
    }
    __syncthreads();

    const float4* __restrict__ img4 = (const float4*)img;
    float4*       __restrict__ out4 = (float4*)out;

    if (base + CPC <= totalCells) {
        // Fast path: no guards -> front-batched loads across all 4 iterations.
        #pragma unroll
        for (int j = 0; j < (CPC * (CC / 4)) / THREADS; ++j) {   // 4 iters
            int i   = j * THREADS + tid;
            int cl  = i >> 7;        // local cell (0..7)
            int t4  = i & 127;       // float4 lane within cell
            int4   o = s_off[cl];
            float4 w = s_w[cl];

            float4 a = __ldg(img4 + o.x + t4);
            float4 b = __ldg(img4 + o.y + t4);
            float4 c = __ldg(img4 + o.z + t4);
            float4 d = __ldg(img4 + o.w + t4);

            float4 r;
            r.x = w.x * a.x + w.y * b.x + w.z * c.x + w.w * d.x;
            r.y = w.x * a.y + w.y * b.y + w.z * c.y + w.w * d.y;
            r.z = w.x * a.z + w.y * b.z + w.z * c.z + w.w * d.z;
            r.w = w.x * a.w + w.y * b.w + w.z * c.w + w.w * d.w;

            __stcs(out4 + (size_t)(base + cl) * (CC / 4) + t4, r);
        }
    } else {
        // Tail CTA (only if totalCells % CPC != 0).
        for (int j = 0; j < (CPC * (CC / 4)) / THREADS; ++j) {
            int i    = j * THREADS + tid;
            int cl   = i >> 7;
            int t4   = i & 127;
            int cell = base + cl;
            if (cell >= totalCells) break;
            int4   o = s_off[cl];
            float4 w = s_w[cl];

            float4 a = __ldg(img4 + o.x + t4);
            float4 b = __ldg(img4 + o.y + t4);
            float4 c = __ldg(img4 + o.z + t4);
            float4 d = __ldg(img4 + o.w + t4);

            float4 r;
            r.x = w.x * a.x + w.y * b.x + w.z * c.x + w.w * d.x;
            r.y = w.x * a.y + w.y * b.y + w.z * c.y + w.w * d.y;
            r.z = w.x * a.z + w.y * b.z + w.z * c.z + w.w * d.z;
            r.w = w.x * a.w + w.y * b.w + w.z * c.w + w.w * d.w;

            __stcs(out4 + (size_t)cell * (CC / 4) + t4, r);
        }
    }
}

extern "C" void kernel_launch(void* const* d_in, const int* in_sizes, int n_in,
                              void* d_out, int out_size)
{
    const float* img = (const float*)d_in[0];   // [1,128,128,512] f32
    const float* roi = (const float*)d_in[1];   // [N,4] f32
    float*       out = (float*)d_out;           // [1,N,7,7,512] f32

    int N = in_sizes[1] / 4;
    if (N > NMAX) N = NMAX;
    int totalCells = N * POOL * POOL;
    int grid = (totalCells + CPC - 1) / CPC;

    roi_coords_kernel<<<(N + 255) / 256, 256>>>(roi, N);
    roi_pool_kernel<<<grid, THREADS>>>(img, out, totalCells);
}

// round 6
// speedup vs baseline: 1.1292x; 1.0183x over previous
#include <cuda_runtime.h>

// image [1,128,128,512] f32 NHWC, RoI [N,4] f32 (cx,cy,w,h), POOL=7, STRIDE=16.
#define POOL   7
#define HH     128
#define WW     128
#define CC     512
#define NMAX   1024
#define CPC    8          // cells per CTA (49000 % 8 handled by guarded path)
#define THREADS 256

// Scratch (__device__ globals per allocation-free rule).
__device__ int   g_iy0[NMAX * POOL];
__device__ int   g_iy1[NMAX * POOL];
__device__ float g_ly [NMAX * POOL];
__device__ int   g_ix0[NMAX * POOL];
__device__ int   g_ix1[NMAX * POOL];
__device__ float g_lx [NMAX * POOL];

// ---------------------------------------------------------------------------
// Kernel 1: per-ROI bilinear sample coordinates (matches reference exactly).
// ---------------------------------------------------------------------------
__global__ void roi_coords_kernel(const float* __restrict__ roi, int N)
{
    int n = blockIdx.x * blockDim.x + threadIdx.x;
    if (n >= N) return;

    const float inv_stride = 1.0f / 16.0f;
    float cx = roi[n * 4 + 0];
    float cy = roi[n * 4 + 1];
    float w  = roi[n * 4 + 2];
    float h  = roi[n * 4 + 3];

    float r  = rintf((cx - 0.5f * w) * inv_stride);   // x-start (col)
    float c  = rintf((cy - 0.5f * h) * inv_stride);   // y-start (row)
    float wq = fmaxf(rintf(w * inv_stride), 1.0f);
    float hq = fmaxf(rintf(h * inv_stride), 1.0f);

    #pragma unroll
    for (int p = 0; p < POOL; ++p) {
        float g = (p + 0.5f) / (float)POOL;
        {   // y axis (rows, limit HH)
            float s  = fminf(fmaxf(g * hq - 0.5f, 0.0f), hq - 1.0f);
            float f0 = floorf(s);
            float fr = s - f0;
            float f1 = fminf(f0 + 1.0f, hq - 1.0f);
            g_iy0[n * POOL + p] = (int)fminf(fmaxf(c + f0, 0.0f), (float)(HH - 1));
            g_iy1[n * POOL + p] = (int)fminf(fmaxf(c + f1, 0.0f), (float)(HH - 1));
            g_ly [n * POOL + p] = fr;
        }
        {   // x axis (cols, limit WW)
            float s  = fminf(fmaxf(g * wq - 0.5f, 0.0f), wq - 1.0f);
            float f0 = floorf(s);
            float fr = s - f0;
            float f1 = fminf(f0 + 1.0f, wq - 1.0f);
            g_ix0[n * POOL + p] = (int)fminf(fmaxf(r + f0, 0.0f), (float)(WW - 1));
            g_ix1[n * POOL + p] = (int)fminf(fmaxf(r + f1, 0.0f), (float)(WW - 1));
            g_lx [n * POOL + p] = fr;
        }
    }
}

// ---------------------------------------------------------------------------
// Kernel 2: 8 cells per CTA, 256 threads, 4 float4 items/thread fully
// unrolled -> 16 independent LDG.128 in flight per thread (latency hiding).
// Cell params precomputed into smem by 8 threads (kills per-thread IMADs).
// ---------------------------------------------------------------------------
__global__ __launch_bounds__(THREADS)
void roi_pool_kernel(const float* __restrict__ img, float* __restrict__ out,
                     int totalCells)
{
    __shared__ int4   s_off[CPC];   // corner offsets in float4 units
    __shared__ float4 s_w[CPC];     // bilinear weights

    const int base = blockIdx.x * CPC;
    const int tid  = threadIdx.x;

    if (tid < CPC) {
        int cell = base + tid;
        if (cell < totalCells) {
            int n   = cell / (POOL * POOL);
            int rem = cell - n * (POOL * POOL);
            int py  = rem / POOL;
            int px  = rem - py * POOL;

            int   iy0 = g_iy0[n * POOL + py];
            int   iy1 = g_iy1[n * POOL + py];
            float ly  = g_ly [n * POOL + py];
            int   ix0 = g_ix0[n * POOL + px];
            int   ix1 = g_ix1[n * POOL + px];
            float lx  = g_lx [n * POOL + px];

            // float4-unit offsets: (iy*WW + ix) * (CC/4)
            s_off[tid] = make_int4((iy0 * WW + ix0) * (CC / 4),
                                   (iy0 * WW + ix1) * (CC / 4),
                                   (iy1 * WW + ix0) * (CC / 4),
                                   (iy1 * WW + ix1) * (CC / 4));
            s_w[tid] = make_float4((1.0f - ly) * (1.0f - lx),
                                   (1.0f - ly) * lx,
                                   ly * (1.0f - lx),
                                   ly * lx);
        }
    }
    __syncthreads();

    const float4* __restrict__ img4 = (const float4*)img;
    float4*       __restrict__ out4 = (float4*)out;

    if (base + CPC <= totalCells) {
        // Fast path: no guards -> front-batched loads across all 4 iterations.
        #pragma unroll
        for (int j = 0; j < (CPC * (CC / 4)) / THREADS; ++j) {   // 4 iters
            int i   = j * THREADS + tid;
            int cl  = i >> 7;        // local cell (0..7)
            int t4  = i & 127;       // float4 lane within cell
            int4   o = s_off[cl];
            float4 w = s_w[cl];

            float4 a = __ldg(img4 + o.x + t4);
            float4 b = __ldg(img4 + o.y + t4);
            float4 c = __ldg(img4 + o.z + t4);
            float4 d = __ldg(img4 + o.w + t4);

            float4 r;
            r.x = w.x * a.x + w.y * b.x + w.z * c.x + w.w * d.x;
            r.y = w.x * a.y + w.y * b.y + w.z * c.y + w.w * d.y;
            r.z = w.x * a.z + w.y * b.z + w.z * c.z + w.w * d.z;
            r.w = w.x * a.w + w.y * b.w + w.z * c.w + w.w * d.w;

            __stcs(out4 + (size_t)(base + cl) * (CC / 4) + t4, r);
        }
    } else {
        // Tail CTA (only if totalCells % CPC != 0).
        for (int j = 0; j < (CPC * (CC / 4)) / THREADS; ++j) {
            int i    = j * THREADS + tid;
            int cl   = i >> 7;
            int t4   = i & 127;
            int cell = base + cl;
            if (cell >= totalCells) break;
            int4   o = s_off[cl];
            float4 w = s_w[cl];

            float4 a = __ldg(img4 + o.x + t4);
            float4 b = __ldg(img4 + o.y + t4);
            float4 c = __ldg(img4 + o.z + t4);
            float4 d = __ldg(img4 + o.w + t4);

            float4 r;
            r.x = w.x * a.x + w.y * b.x + w.z * c.x + w.w * d.x;
            r.y = w.x * a.y + w.y * b.y + w.z * c.y + w.w * d.y;
            r.z = w.x * a.z + w.y * b.z + w.z * c.z + w.w * d.z;
            r.w = w.x * a.w + w.y * b.w + w.z * c.w + w.w * d.w;

            __stcs(out4 + (size_t)cell * (CC / 4) + t4, r);
        }
    }
}

extern "C" void kernel_launch(void* const* d_in, const int* in_sizes, int n_in,
                              void* d_out, int out_size)
{
    const float* img = (const float*)d_in[0];   // [1,128,128,512] f32
    const float* roi = (const float*)d_in[1];   // [N,4] f32
    float*       out = (float*)d_out;           // [1,N,7,7,512] f32

    int N = in_sizes[1] / 4;
    if (N > NMAX) N = NMAX;
    int totalCells = N * POOL * POOL;
    int grid = (totalCells + CPC - 1) / CPC;

    roi_coords_kernel<<<(N + 255) / 256, 256>>>(roi, N);
    roi_pool_kernel<<<grid, THREADS>>>(img, out, totalCells);
}

// round 7
// speedup vs baseline: 1.2636x; 1.1190x over previous
#include <cuda_runtime.h>

// image [1,128,128,512] f32 NHWC, RoI [N,4] f32 (cx,cy,w,h), POOL=7, STRIDE=16.
#define POOL    7
#define HH      128
#define WW      128
#define CC      512
#define NMAX    1024
#define MAXCELL (NMAX * POOL * POOL)

// Per-cell params (allocation-free rule: __device__ globals).
__device__ int4   g_off[MAXCELL];   // 4 corner offsets, float4 units
__device__ float4 g_w  [MAXCELL];   // 4 bilinear weights

// ---------------------------------------------------------------------------
// Kernel 1: one thread per (roi, py, px) cell. Computes bilinear corner
// offsets + weights, exactly matching the reference math:
//   start = round((center - size/2)/16)   (rintf == round-half-even)
//   q     = max(round(size/16), 1)
//   s     = clip(((p+0.5)/7)*q - 0.5, 0, q-1); f0=floor(s); frac=s-f0
//   f1    = min(f0+1, q-1); idx = clip(start + f, 0, limit-1)
// ---------------------------------------------------------------------------
__global__ void roi_prep_kernel(const float* __restrict__ roi, int totalCells)
{
    int cell = blockIdx.x * blockDim.x + threadIdx.x;
    if (cell >= totalCells) return;

    int n   = cell / (POOL * POOL);
    int rem = cell - n * (POOL * POOL);
    int py  = rem / POOL;
    int px  = rem - py * POOL;

    const float inv_stride = 1.0f / 16.0f;
    float cx = roi[n * 4 + 0];
    float cy = roi[n * 4 + 1];
    float w  = roi[n * 4 + 2];
    float h  = roi[n * 4 + 3];

    float r  = rintf((cx - 0.5f * w) * inv_stride);   // x start (col)
    float c  = rintf((cy - 0.5f * h) * inv_stride);   // y start (row)
    float wq = fmaxf(rintf(w * inv_stride), 1.0f);
    float hq = fmaxf(rintf(h * inv_stride), 1.0f);

    // y axis (rows, limit HH)
    float gy = (py + 0.5f) / (float)POOL;
    float sy = fminf(fmaxf(gy * hq - 0.5f, 0.0f), hq - 1.0f);
    float fy0 = floorf(sy);
    float ly  = sy - fy0;
    float fy1 = fminf(fy0 + 1.0f, hq - 1.0f);
    int iy0 = (int)fminf(fmaxf(c + fy0, 0.0f), (float)(HH - 1));
    int iy1 = (int)fminf(fmaxf(c + fy1, 0.0f), (float)(HH - 1));

    // x axis (cols, limit WW)
    float gx = (px + 0.5f) / (float)POOL;
    float sx = fminf(fmaxf(gx * wq - 0.5f, 0.0f), wq - 1.0f);
    float fx0 = floorf(sx);
    float lx  = sx - fx0;
    float fx1 = fminf(fx0 + 1.0f, wq - 1.0f);
    int ix0 = (int)fminf(fmaxf(r + fx0, 0.0f), (float)(WW - 1));
    int ix1 = (int)fminf(fmaxf(r + fx1, 0.0f), (float)(WW - 1));

    g_off[cell] = make_int4((iy0 * WW + ix0) * (CC / 4),
                            (iy0 * WW + ix1) * (CC / 4),
                            (iy1 * WW + ix0) * (CC / 4),
                            (iy1 * WW + ix1) * (CC / 4));
    g_w[cell] = make_float4((1.0f - ly) * (1.0f - lx),
                            (1.0f - ly) * lx,
                            ly * (1.0f - lx),
                            ly * lx);
}

// ---------------------------------------------------------------------------
// Kernel 2: 64 threads per cell, each thread owns 2 float4 lanes (t4, t4+64).
// Straight-line body: 2 broadcast param loads, then 8 INDEPENDENT data
// LDG.128 front-batched in registers, 24 FFMA, 2 streaming STG.128.
// No smem, no syncthreads, no loop -> compiler must keep all 8 loads in
// flight (MLP=8/thread).
// ---------------------------------------------------------------------------
__global__ __launch_bounds__(256)
void roi_pool_kernel(const float* __restrict__ img, float* __restrict__ out,
                     int totalCells)
{
    int tid  = threadIdx.x;
    int cell = blockIdx.x * 4 + (tid >> 6);
    if (cell >= totalCells) return;
    int t4   = tid & 63;               // first lane; second is t4+64

    int4   o = g_off[cell];            // broadcast across 64 threads
    float4 w = g_w[cell];

    const float4* __restrict__ img4 = (const float4*)img;

    // 8 independent loads (4 corners x 2 lanes)
    float4 a0 = __ldg(img4 + o.x + t4);
    float4 b0 = __ldg(img4 + o.y + t4);
    float4 c0 = __ldg(img4 + o.z + t4);
    float4 d0 = __ldg(img4 + o.w + t4);
    float4 a1 = __ldg(img4 + o.x + t4 + 64);
    float4 b1 = __ldg(img4 + o.y + t4 + 64);
    float4 c1 = __ldg(img4 + o.z + t4 + 64);
    float4 d1 = __ldg(img4 + o.w + t4 + 64);

    float4 r0, r1;
    r0.x = w.x * a0.x + w.y * b0.x + w.z * c0.x + w.w * d0.x;
    r0.y = w.x * a0.y + w.y * b0.y + w.z * c0.y + w.w * d0.y;
    r0.z = w.x * a0.z + w.y * b0.z + w.z * c0.z + w.w * d0.z;
    r0.w = w.x * a0.w + w.y * b0.w + w.z * c0.w + w.w * d0.w;
    r1.x = w.x * a1.x + w.y * b1.x + w.z * c1.x + w.w * d1.x;
    r1.y = w.x * a1.y + w.y * b1.y + w.z * c1.y + w.w * d1.y;
    r1.z = w.x * a1.z + w.y * b1.z + w.z * c1.z + w.w * d1.z;
    r1.w = w.x * a1.w + w.y * b1.w + w.z * c1.w + w.w * d1.w;

    float4* __restrict__ out4 = (float4*)out + (size_t)cell * (CC / 4);
    __stcs(out4 + t4,      r0);
    __stcs(out4 + t4 + 64, r1);
}

extern "C" void kernel_launch(void* const* d_in, const int* in_sizes, int n_in,
                              void* d_out, int out_size)
{
    const float* img = (const float*)d_in[0];   // [1,128,128,512] f32
    const float* roi = (const float*)d_in[1];   // [N,4] f32
    float*       out = (float*)d_out;           // [1,N,7,7,512] f32

    int N = in_sizes[1] / 4;
    if (N > NMAX) N = NMAX;
    int totalCells = N * POOL * POOL;

    roi_prep_kernel<<<(totalCells + 255) / 256, 256>>>(roi, totalCells);
    roi_pool_kernel<<<(totalCells + 3) / 4, 256>>>(img, out, totalCells);
}